// round 1
// baseline (speedup 1.0000x reference)
#include <cuda_runtime.h>
#include <math.h>

// Problem shape (from reference setup_inputs)
#define BB 512       // batch rows
#define TT_TOTAL 32768
#define NC 256       // chunks per row == threads per block
#define LCH 128      // samples per chunk (TT_TOTAL / NC)
#define TILE_T 16    // time samples per smem tile
#define NTILES (LCH / TILE_T)   // 8 tiles per phase
#define XS_STRIDE (TILE_T + 1)  // 17, pad to kill bank conflicts on strided reads

__global__ __launch_bounds__(NC) void dsvf_scan_kernel(
    const float* __restrict__ x,
    const float* __restrict__ gp,
    const float* __restrict__ rp,
    const float* __restrict__ mhpp,
    const float* __restrict__ mbpp,
    const float* __restrict__ mlpp,
    float* __restrict__ y)
{
    __shared__ float xs[NC * XS_STRIDE];   // x tile, [chunk][t] with pad
    __shared__ float ys[NC * XS_STRIDE];   // y tile
    __shared__ float2 sv[NC];              // scan states

    const int tid = threadIdx.x;
    const int row = blockIdx.x;
    const float* __restrict__ xrow = x + (size_t)row * TT_TOTAL;
    float* __restrict__ yrow = y + (size_t)row * TT_TOTAL;

    // ---- coefficients (computed redundantly per thread; negligible) ----
    const float graw = *gp;
    const float rraw = *rp;
    const float m_hp = *mhpp;
    const float m_bp = *mbpp;
    const float m_lp = *mlpp;

    const float sig = 1.0f / (1.0f + expf(-graw));
    const float gg  = tanf(1.57079632679489662f * sig);     // tan(pi*sig/2)
    // softplus, numerically robust
    const float rr  = fmaxf(rraw, 0.0f) + log1pf(expf(-fabsf(rraw)));

    const float g2 = gg * gg;
    float b0 = g2 * m_lp + gg * m_bp + m_hp;
    float b1 = 2.0f * g2 * m_lp - 2.0f * m_hp;
    float b2 = g2 * m_lp - gg * m_bp + m_hp;
    const float a0 = g2 + 2.0f * rr * gg + 1.0f;
    float a1 = 2.0f * g2 - 2.0f;
    float a2 = g2 - 2.0f * rr * gg + 1.0f;
    const float inv = 1.0f / a0;
    b0 *= inv; b1 *= inv; b2 *= inv; a1 *= inv; a2 *= inv;

    // state-only update coeffs: z1' = c1*x - a1*z1 + z2 ; z2' = c2*x - a2*z1
    const float c1 = b1 - a1 * b0;
    const float c2 = b2 - a2 * b0;

    // ================= Phase A: zero-state particular solution =================
    float z1 = 0.0f, z2 = 0.0f;
    const int chunk_base = tid * LCH;

    #pragma unroll 1
    for (int tile = 0; tile < NTILES; ++tile) {
        const int t0 = tile * TILE_T;
        // cooperative coalesced load: 1024 float4s, 4 per thread
        #pragma unroll
        for (int it = 0; it < 4; ++it) {
            const int fid = tid + NC * it;     // 0..1023
            const int c = fid >> 2;            // chunk
            const int q = fid & 3;             // quarter within tile
            const float4 v = *reinterpret_cast<const float4*>(xrow + c * LCH + t0 + q * 4);
            float* dst = &xs[c * XS_STRIDE + q * 4];
            dst[0] = v.x; dst[1] = v.y; dst[2] = v.z; dst[3] = v.w;
        }
        __syncthreads();
        #pragma unroll
        for (int t = 0; t < TILE_T; ++t) {
            const float xv = xs[tid * XS_STRIDE + t];
            const float t1  = fmaf(-a1, z1, z2);
            const float nz2 = fmaf(-a2, z1, c2 * xv);
            z1 = fmaf(c1, xv, t1);
            z2 = nz2;
        }
        __syncthreads();
    }

    // ================= Combine: block-wide affine Kogge-Stone scan =============
    // Transition matrix G = [[-a1, 1], [-a2, 0]]; need H = G^LCH = G^128 (7 squarings)
    float h00 = -a1, h01 = 1.0f, h10 = -a2, h11 = 0.0f;
    #pragma unroll
    for (int i = 0; i < 7; ++i) {
        const float n00 = h00 * h00 + h01 * h10;
        const float n01 = h00 * h01 + h01 * h11;
        const float n10 = h10 * h00 + h11 * h10;
        const float n11 = h10 * h01 + h11 * h11;
        h00 = n00; h01 = n01; h10 = n10; h11 = n11;
    }

    float2 acc = make_float2(z1, z2);   // particular state of this chunk
    sv[tid] = acc;
    __syncthreads();

    #pragma unroll
    for (int k = 0; k < 8; ++k) {       // 2^8 = 256 = NC
        const int off = 1 << k;
        float2 other = make_float2(0.0f, 0.0f);
        if (tid >= off) other = sv[tid - off];
        __syncthreads();
        acc.x = fmaf(h00, other.x, fmaf(h01, other.y, acc.x));
        acc.y = fmaf(h10, other.x, fmaf(h11, other.y, acc.y));
        sv[tid] = acc;
        // H = H^2 for next doubling step
        const float n00 = h00 * h00 + h01 * h10;
        const float n01 = h00 * h01 + h01 * h11;
        const float n10 = h10 * h00 + h11 * h10;
        const float n11 = h10 * h01 + h11 * h11;
        h00 = n00; h01 = n01; h10 = n10; h11 = n11;
        __syncthreads();
    }

    // exclusive prefix = true start state of this chunk
    float2 s0 = make_float2(0.0f, 0.0f);
    if (tid > 0) s0 = sv[tid - 1];
    z1 = s0.x;
    z2 = s0.y;
    __syncthreads();

    // ================= Phase B: rerun with true state, emit y ==================
    #pragma unroll 1
    for (int tile = 0; tile < NTILES; ++tile) {
        const int t0 = tile * TILE_T;
        #pragma unroll
        for (int it = 0; it < 4; ++it) {
            const int fid = tid + NC * it;
            const int c = fid >> 2;
            const int q = fid & 3;
            const float4 v = *reinterpret_cast<const float4*>(xrow + c * LCH + t0 + q * 4);
            float* dst = &xs[c * XS_STRIDE + q * 4];
            dst[0] = v.x; dst[1] = v.y; dst[2] = v.z; dst[3] = v.w;
        }
        __syncthreads();
        #pragma unroll
        for (int t = 0; t < TILE_T; ++t) {
            const float xv = xs[tid * XS_STRIDE + t];
            const float yv = fmaf(b0, xv, z1);
            const float nz1 = fmaf(b1, xv, fmaf(-a1, yv, z2));
            const float nz2 = fmaf(b2, xv, -a2 * yv);
            ys[tid * XS_STRIDE + t] = yv;
            z1 = nz1;
            z2 = nz2;
        }
        __syncthreads();
        // cooperative coalesced store of y tile
        #pragma unroll
        for (int it = 0; it < 4; ++it) {
            const int fid = tid + NC * it;
            const int c = fid >> 2;
            const int q = fid & 3;
            const float* src = &ys[c * XS_STRIDE + q * 4];
            float4 v;
            v.x = src[0]; v.y = src[1]; v.z = src[2]; v.w = src[3];
            *reinterpret_cast<float4*>(yrow + c * LCH + t0 + q * 4) = v;
        }
        // no extra sync needed: next tile's load targets xs (distinct array),
        // and the post-load __syncthreads orders ys reuse.
    }
    (void)chunk_base;
}

extern "C" void kernel_launch(void* const* d_in, const int* in_sizes, int n_in,
                              void* d_out, int out_size) {
    const float* x    = (const float*)d_in[0];   // [512, 32768]
    const float* g    = (const float*)d_in[1];
    const float* r    = (const float*)d_in[2];
    const float* m_hp = (const float*)d_in[3];
    const float* m_bp = (const float*)d_in[4];
    const float* m_lp = (const float*)d_in[5];
    float* y = (float*)d_out;

    dsvf_scan_kernel<<<BB, NC>>>(x, g, r, m_hp, m_bp, m_lp, y);
}